// round 5
// baseline (speedup 1.0000x reference)
#include <cuda_runtime.h>
#include <math.h>

// Allpass biquad over [B, 1, T] fp32, T = 480000.
// Thread-serial: each thread owns an independent contiguous 32-sample segment
// (poles decay 0.414/sample -> 16-sample warm-up reconstructs state to ~7.5e-7).
// Segment-major smem staging: stage-in is an identity gmem->smem copy (STS.128),
// recurrence uses LDS.128/STS.128 in-place, gather-out LDS.128 -> STG.128.
// Pad of 4 floats per segment makes every phase bank-conflict-free.

#define T_LEN    480000
#define SEG      32                 // samples per thread
#define NTHREADS 256
#define CHUNK    (SEG * NTHREADS)   // 8192 samples per block
#define CHUNKS_PER_ROW 59           // 58 full + tail of 4864 (152 segments)
#define WARM     16
#define SSTRIDE  (SEG + 4)          // 36 floats; 36 % 32 = 4 -> conflict-free
#define SMEM_FLOATS (NTHREADS * SSTRIDE)   // 9216 floats = 36864 B

__global__ void __launch_bounds__(NTHREADS, 6)
allpass_kernel(const float* __restrict__ x, float* __restrict__ y,
               float b0, float b1, float b2, float a1, float a2)
{
    __shared__ float sm[SMEM_FLOATS];   // sm[seg * SSTRIDE + k]
    const int tid   = threadIdx.x;
    const int chunk = blockIdx.x;
    const int row   = blockIdx.y;

    const float* xr = x + (size_t)row * T_LEN;
    float*       yr = y + (size_t)row * T_LEN;
    const int base      = chunk * CHUNK;
    const int chunk_len = min(CHUNK, T_LEN - base);   // 8192 or 4864
    const int n_seg     = chunk_len >> 5;             // 256 or 152

    // ---- stage-in: coalesced LDG.128 -> STS.128 (identity copy) ----
    #pragma unroll
    for (int r = 0; r < 8; r++) {
        const int j = (r * NTHREADS + tid) * 4;   // float index in chunk
        if (j < chunk_len) {
            const float4 v = __ldcs(reinterpret_cast<const float4*>(xr + base + j));
            const int seg = j >> 5;
            const int k   = j & 31;
            *reinterpret_cast<float4*>(&sm[seg * SSTRIDE + k]) = v;
        }
    }
    __syncthreads();

    // ---- warm-up: 16 serial samples establish (y1,y2,x1,x2) ----
    const int i = tid;
    float y1 = 0.0f, y2 = 0.0f, x1 = 0.0f, x2 = 0.0f;
    if (i < n_seg) {
        if (i > 0) {
            const float* w = &sm[(i - 1) * SSTRIDE + (SEG - WARM)];
            #pragma unroll
            for (int k = 0; k < WARM; k++) {
                const float xv = w[k];
                const float yn = b0 * xv + b1 * x1 + b2 * x2
                               - a1 * y1 - a2 * y2;
                y2 = y1; y1 = yn; x2 = x1; x1 = xv;
            }
        } else if (chunk > 0) {
            #pragma unroll
            for (int k = 0; k < WARM; k++) {
                const float xv = __ldg(xr + base - WARM + k);
                const float yn = b0 * xv + b1 * x1 + b2 * x2
                               - a1 * y1 - a2 * y2;
                y2 = y1; y1 = yn; x2 = x1; x1 = xv;
            }
        }
        // chunk == 0, seg 0: true zero initial state
    }
    __syncthreads();   // warm-up reads finish before in-place overwrite

    // ---- recurrence: 32 samples, LDS.128 / STS.128 in-place ----
    if (i < n_seg) {
        float* s = &sm[i * SSTRIDE];
        #pragma unroll
        for (int k4 = 0; k4 < SEG / 4; k4++) {
            float4 v = *reinterpret_cast<float4*>(s + k4 * 4);
            float yn;
            yn  = b0 * v.x + b1 * x1 + b2 * x2 - a1 * y1 - a2 * y2;
            y2 = y1; y1 = yn; x2 = x1; x1 = v.x; v.x = yn;
            yn  = b0 * v.y + b1 * x1 + b2 * x2 - a1 * y1 - a2 * y2;
            y2 = y1; y1 = yn; x2 = x1; x1 = v.y; v.y = yn;
            yn  = b0 * v.z + b1 * x1 + b2 * x2 - a1 * y1 - a2 * y2;
            y2 = y1; y1 = yn; x2 = x1; x1 = v.z; v.z = yn;
            yn  = b0 * v.w + b1 * x1 + b2 * x2 - a1 * y1 - a2 * y2;
            y2 = y1; y1 = yn; x2 = x1; x1 = v.w; v.w = yn;
            *reinterpret_cast<float4*>(s + k4 * 4) = v;
        }
    }
    __syncthreads();

    // ---- gather-out: LDS.128 -> coalesced STG.128 ----
    #pragma unroll
    for (int r = 0; r < 8; r++) {
        const int j = (r * NTHREADS + tid) * 4;
        if (j < chunk_len) {
            const int seg = j >> 5;
            const int k   = j & 31;
            const float4 v = *reinterpret_cast<const float4*>(&sm[seg * SSTRIDE + k]);
            __stcs(reinterpret_cast<float4*>(yr + base + j), v);
        }
    }
}

extern "C" void kernel_launch(void* const* d_in, const int* in_sizes, int n_in,
                              void* d_out, int out_size)
{
    const float* x = (const float*)d_in[0];
    float* y = (float*)d_out;

    const int total = in_sizes[0];
    const int B = total / T_LEN;   // 64

    // Coefficients in float64 then cast, matching the numpy reference.
    const double w0    = 2.0 * M_PI * 4000.0 / 16000.0;
    const double alpha = sin(w0) / (2.0 * 0.707);
    const double cw0   = cos(w0);
    const double a0d   = 1.0 + alpha;
    const float b0 = (float)((1.0 - alpha) / a0d);
    const float b1 = (float)((-2.0 * cw0) / a0d);
    const float b2 = (float)((1.0 + alpha) / a0d);
    const float a1 = (float)((-2.0 * cw0) / a0d);
    const float a2 = (float)((1.0 - alpha) / a0d);

    dim3 grid(CHUNKS_PER_ROW, B);
    allpass_kernel<<<grid, NTHREADS>>>(x, y, b0, b1, b2, a1, a2);
}

// round 6
// speedup vs baseline: 1.0815x; 1.0815x over previous
#include <cuda_runtime.h>
#include <math.h>

// Allpass biquad over [B, 1, T] fp32, T = 480000.
// Thread-serial segments (32 samples/thread, 16-sample warm-up; poles decay
// 0.414/sample so warm-up truncation ~7.5e-7), smem-staged for coalescing.
// R6: persistent chunk loop + double-buffered cp.async pipeline so DRAM
// traffic of chunk c+1 overlaps the compute phases of chunk c.

#define T_LEN    480000
#define SEG      32
#define NTHREADS 256
#define CHUNK    (SEG * NTHREADS)        // 8192 samples per chunk
#define CHUNKS_PER_ROW 59                // 58 full + tail of 4864
#define WARM     16
#define SSTRIDE  (SEG + 4)               // 36: conflict-free phases
#define SEG_FLOATS   (NTHREADS * SSTRIDE)   // 9216
#define TAIL_OFF     SEG_FLOATS             // 16-float prev-tail slot
#define STAGE_FLOATS (SEG_FLOATS + 32)      // 9248 (16B-aligned stage)

__device__ __forceinline__ void cp_async16(float* dst_smem, const float* src) {
    unsigned d = (unsigned)__cvta_generic_to_shared(dst_smem);
    asm volatile("cp.async.cg.shared.global [%0], [%1], 16;\n"
                 :: "r"(d), "l"(src) : "memory");
}

__global__ void __launch_bounds__(NTHREADS, 3)
allpass_kernel(const float* __restrict__ x, float* __restrict__ y,
               float b0, float b1, float b2, float a1, float a2,
               int total_chunks)
{
    extern __shared__ float sm[];        // 2 stages of STAGE_FLOATS
    const int tid = threadIdx.x;

    // issue cp.async copies for linear chunk idx into stage buffer
    auto issue = [&](int idx, int buf) {
        const int row  = idx / CHUNKS_PER_ROW;
        const int ch   = idx % CHUNKS_PER_ROW;
        const float* xr = x + (size_t)row * T_LEN;
        const int base = ch * CHUNK;
        const int clen = min(CHUNK, T_LEN - base);
        float* sb = sm + buf * STAGE_FLOATS;
        #pragma unroll
        for (int r = 0; r < 8; r++) {
            const int j = (r * NTHREADS + tid) * 4;
            if (j < clen) {
                const int seg = j >> 5;
                const int k   = j & 31;
                cp_async16(&sb[seg * SSTRIDE + k], xr + base + j);
            }
        }
        if (ch > 0 && tid < 4)   // prev-chunk tail (for thread 0's warm-up)
            cp_async16(&sb[TAIL_OFF + tid * 4], xr + base - WARM + tid * 4);
    };

    int first = blockIdx.x;
    if (first < total_chunks) issue(first, 0);
    asm volatile("cp.async.commit_group;\n" ::: "memory");

    int c = 0;
    for (int idx = first; idx < total_chunks; idx += gridDim.x, ++c) {
        // prefetch next chunk into the other buffer; commit unconditionally
        const int nidx = idx + gridDim.x;
        if (nidx < total_chunks) issue(nidx, (c + 1) & 1);
        asm volatile("cp.async.commit_group;\n" ::: "memory");
        // current chunk's group complete when <=1 group pending
        asm volatile("cp.async.wait_group 1;\n" ::: "memory");
        __syncthreads();

        const int row  = idx / CHUNKS_PER_ROW;
        const int ch   = idx % CHUNKS_PER_ROW;
        const int base = ch * CHUNK;
        const int clen = min(CHUNK, T_LEN - base);
        const int n_seg = clen >> 5;
        float* sb = sm + (c & 1) * STAGE_FLOATS;
        float* yr = y + (size_t)row * T_LEN;

        // ---- warm-up: 16 serial samples from prev segment's tail ----
        float y1 = 0.0f, y2 = 0.0f, x1 = 0.0f, x2 = 0.0f;
        if (tid < n_seg && (tid > 0 || ch > 0)) {
            const float* w = (tid > 0) ? &sb[(tid - 1) * SSTRIDE + (SEG - WARM)]
                                       : &sb[TAIL_OFF];
            #pragma unroll
            for (int k = 0; k < WARM; k++) {
                const float xv = w[k];
                const float yn = b0 * xv + b1 * x1 + b2 * x2
                               - a1 * y1 - a2 * y2;
                y2 = y1; y1 = yn; x2 = x1; x1 = xv;
            }
        }
        __syncthreads();   // neighbor-tail reads before in-place overwrite

        // ---- recurrence: 32 samples, LDS.128 / STS.128 in place ----
        if (tid < n_seg) {
            float* s = &sb[tid * SSTRIDE];
            #pragma unroll
            for (int k4 = 0; k4 < SEG / 4; k4++) {
                float4 v = *reinterpret_cast<float4*>(s + k4 * 4);
                float yn;
                yn = b0 * v.x + b1 * x1 + b2 * x2 - a1 * y1 - a2 * y2;
                y2 = y1; y1 = yn; x2 = x1; x1 = v.x; v.x = yn;
                yn = b0 * v.y + b1 * x1 + b2 * x2 - a1 * y1 - a2 * y2;
                y2 = y1; y1 = yn; x2 = x1; x1 = v.y; v.y = yn;
                yn = b0 * v.z + b1 * x1 + b2 * x2 - a1 * y1 - a2 * y2;
                y2 = y1; y1 = yn; x2 = x1; x1 = v.z; v.z = yn;
                yn = b0 * v.w + b1 * x1 + b2 * x2 - a1 * y1 - a2 * y2;
                y2 = y1; y1 = yn; x2 = x1; x1 = v.w; v.w = yn;
                *reinterpret_cast<float4*>(s + k4 * 4) = v;
            }
        }
        __syncthreads();

        // ---- gather-out: LDS.128 -> coalesced streaming STG.128 ----
        #pragma unroll
        for (int r = 0; r < 8; r++) {
            const int j = (r * NTHREADS + tid) * 4;
            if (j < clen) {
                const int seg = j >> 5;
                const int k   = j & 31;
                const float4 v =
                    *reinterpret_cast<const float4*>(&sb[seg * SSTRIDE + k]);
                __stcs(reinterpret_cast<float4*>(yr + base + j), v);
            }
        }
        __syncthreads();   // buffer reused by the prefetch 2 iters ahead
    }
}

extern "C" void kernel_launch(void* const* d_in, const int* in_sizes, int n_in,
                              void* d_out, int out_size)
{
    const float* x = (const float*)d_in[0];
    float* y = (float*)d_out;

    const int total = in_sizes[0];
    const int B = total / T_LEN;   // 64

    // Coefficients in float64 then cast, matching the numpy reference.
    const double w0    = 2.0 * M_PI * 4000.0 / 16000.0;
    const double alpha = sin(w0) / (2.0 * 0.707);
    const double cw0   = cos(w0);
    const double a0d   = 1.0 + alpha;
    const float b0 = (float)((1.0 - alpha) / a0d);
    const float b1 = (float)((-2.0 * cw0) / a0d);
    const float b2 = (float)((1.0 + alpha) / a0d);
    const float a1 = (float)((-2.0 * cw0) / a0d);
    const float a2 = (float)((1.0 - alpha) / a0d);

    const int smem_bytes = 2 * STAGE_FLOATS * (int)sizeof(float);  // ~74 KB
    static bool attr_set = false;
    if (!attr_set) {
        cudaFuncSetAttribute(allpass_kernel,
                             cudaFuncAttributeMaxDynamicSharedMemorySize,
                             smem_bytes);
        attr_set = true;
    }

    const int total_chunks = B * CHUNKS_PER_ROW;   // 3776
    const int grid = 148 * 3;                      // 3 blocks/SM, one wave

    allpass_kernel<<<grid, NTHREADS, smem_bytes>>>(x, y, b0, b1, b2, a1, a2,
                                                   total_chunks);
}

// round 8
// speedup vs baseline: 1.1451x; 1.0588x over previous
#include <cuda_runtime.h>
#include <math.h>

// Allpass biquad over [B, 1, T] fp32, T = 480000.
// Thread-serial segments (32 samples/thread, 16-sample warm-up; poles decay
// 0.414/sample so warm-up truncation ~7.5e-7), smem-staged for coalescing,
// double-buffered cp.async pipeline (R6), plus dynamic chunk self-scheduling
// via a global atomic counter to kill the persistent-block straggler tail (R7).

#define T_LEN    480000
#define SEG      32
#define NTHREADS 256
#define CHUNK    (SEG * NTHREADS)        // 8192 samples per chunk
#define CHUNKS_PER_ROW 59                // 58 full + tail of 4864
#define WARM     16
#define SSTRIDE  (SEG + 4)               // 36: conflict-free phases
#define SEG_FLOATS   (NTHREADS * SSTRIDE)   // 9216
#define TAIL_OFF     SEG_FLOATS             // 16-float prev-tail slot
#define STAGE_FLOATS (SEG_FLOATS + 32)      // 9248 (16B-aligned stage)
#define GRID_BLOCKS  444                    // 148 SMs * 3 blocks

__device__ unsigned int g_chunk_ctr;

__global__ void reset_counter_kernel(unsigned int v) {
    g_chunk_ctr = v;
}

__device__ __forceinline__ void cp_async16(float* dst_smem, const float* src) {
    unsigned d = (unsigned)__cvta_generic_to_shared(dst_smem);
    asm volatile("cp.async.cg.shared.global [%0], [%1], 16;\n"
                 :: "r"(d), "l"(src) : "memory");
}

__global__ void __launch_bounds__(NTHREADS, 3)
allpass_kernel(const float* __restrict__ x, float* __restrict__ y,
               float b0, float b1, float b2, float a1, float a2,
               int total_chunks)
{
    extern __shared__ float sm[];        // 2 stages of STAGE_FLOATS
    __shared__ int s_next;
    const int tid = threadIdx.x;

    auto issue = [&](int idx, int buf) {
        const int row  = idx / CHUNKS_PER_ROW;
        const int ch   = idx % CHUNKS_PER_ROW;
        const float* xr = x + (size_t)row * T_LEN;
        const int base = ch * CHUNK;
        const int clen = min(CHUNK, T_LEN - base);
        float* sb = sm + buf * STAGE_FLOATS;
        #pragma unroll
        for (int r = 0; r < 8; r++) {
            const int j = (r * NTHREADS + tid) * 4;
            if (j < clen) {
                const int seg = j >> 5;
                const int k   = j & 31;
                cp_async16(&sb[seg * SSTRIDE + k], xr + base + j);
            }
        }
        if (ch > 0 && tid < 4)   // prev-chunk tail (for thread 0's warm-up)
            cp_async16(&sb[TAIL_OFF + tid * 4], xr + base - WARM + tid * 4);
    };

    // first chunk is static: blockIdx.x (counter starts at gridDim.x)
    int my = blockIdx.x;
    if (my < total_chunks) issue(my, 0);
    asm volatile("cp.async.commit_group;\n" ::: "memory");

    int buf = 0;
    while (my < total_chunks) {
        // grab + prefetch the next chunk into the other buffer
        if (tid == 0) s_next = (int)atomicAdd(&g_chunk_ctr, 1u);
        __syncthreads();
        const int nidx = s_next;
        if (nidx < total_chunks) issue(nidx, buf ^ 1);
        asm volatile("cp.async.commit_group;\n" ::: "memory");
        asm volatile("cp.async.wait_group 1;\n" ::: "memory");
        __syncthreads();

        const int row  = my / CHUNKS_PER_ROW;
        const int ch   = my % CHUNKS_PER_ROW;
        const int base = ch * CHUNK;
        const int clen = min(CHUNK, T_LEN - base);
        const int n_seg = clen >> 5;
        float* sb = sm + buf * STAGE_FLOATS;
        float* yr = y + (size_t)row * T_LEN;

        // ---- warm-up: 16 serial samples from prev segment's tail ----
        float y1 = 0.0f, y2 = 0.0f, x1 = 0.0f, x2 = 0.0f;
        if (tid < n_seg && (tid > 0 || ch > 0)) {
            const float* w = (tid > 0) ? &sb[(tid - 1) * SSTRIDE + (SEG - WARM)]
                                       : &sb[TAIL_OFF];
            #pragma unroll
            for (int k = 0; k < WARM; k++) {
                const float xv = w[k];
                const float yn = b0 * xv + b1 * x1 + b2 * x2
                               - a1 * y1 - a2 * y2;
                y2 = y1; y1 = yn; x2 = x1; x1 = xv;
            }
        }
        __syncthreads();   // neighbor-tail reads before in-place overwrite

        // ---- recurrence: 32 samples, LDS.128 / STS.128 in place ----
        if (tid < n_seg) {
            float* s = &sb[tid * SSTRIDE];
            #pragma unroll
            for (int k4 = 0; k4 < SEG / 4; k4++) {
                float4 v = *reinterpret_cast<float4*>(s + k4 * 4);
                float yn;
                yn = b0 * v.x + b1 * x1 + b2 * x2 - a1 * y1 - a2 * y2;
                y2 = y1; y1 = yn; x2 = x1; x1 = v.x; v.x = yn;
                yn = b0 * v.y + b1 * x1 + b2 * x2 - a1 * y1 - a2 * y2;
                y2 = y1; y1 = yn; x2 = x1; x1 = v.y; v.y = yn;
                yn = b0 * v.z + b1 * x1 + b2 * x2 - a1 * y1 - a2 * y2;
                y2 = y1; y1 = yn; x2 = x1; x1 = v.z; v.z = yn;
                yn = b0 * v.w + b1 * x1 + b2 * x2 - a1 * y1 - a2 * y2;
                y2 = y1; y1 = yn; x2 = x1; x1 = v.w; v.w = yn;
                *reinterpret_cast<float4*>(s + k4 * 4) = v;
            }
        }
        __syncthreads();

        // ---- gather-out: LDS.128 -> coalesced streaming STG.128 ----
        #pragma unroll
        for (int r = 0; r < 8; r++) {
            const int j = (r * NTHREADS + tid) * 4;
            if (j < clen) {
                const int seg = j >> 5;
                const int k   = j & 31;
                const float4 v =
                    *reinterpret_cast<const float4*>(&sb[seg * SSTRIDE + k]);
                __stcs(reinterpret_cast<float4*>(yr + base + j), v);
            }
        }
        __syncthreads();   // buffer reused by the prefetch next iteration

        my = nidx;
        buf ^= 1;
    }
}

extern "C" void kernel_launch(void* const* d_in, const int* in_sizes, int n_in,
                              void* d_out, int out_size)
{
    const float* x = (const float*)d_in[0];
    float* y = (float*)d_out;

    const int total = in_sizes[0];
    const int B = total / T_LEN;   // 64

    // Coefficients in float64 then cast, matching the numpy reference.
    const double w0    = 2.0 * M_PI * 4000.0 / 16000.0;
    const double alpha = sin(w0) / (2.0 * 0.707);
    const double cw0   = cos(w0);
    const double a0d   = 1.0 + alpha;
    const float b0 = (float)((1.0 - alpha) / a0d);
    const float b1 = (float)((-2.0 * cw0) / a0d);
    const float b2 = (float)((1.0 + alpha) / a0d);
    const float a1 = (float)((-2.0 * cw0) / a0d);
    const float a2 = (float)((1.0 - alpha) / a0d);

    const int smem_bytes = 2 * STAGE_FLOATS * (int)sizeof(float);  // ~74 KB
    static bool attr_set = false;
    if (!attr_set) {
        cudaFuncSetAttribute(allpass_kernel,
                             cudaFuncAttributeMaxDynamicSharedMemorySize,
                             smem_bytes);
        attr_set = true;
    }

    const int total_chunks = B * CHUNKS_PER_ROW;   // 3776

    // counter starts past the statically-assigned first chunks
    reset_counter_kernel<<<1, 1>>>((unsigned int)GRID_BLOCKS);
    allpass_kernel<<<GRID_BLOCKS, NTHREADS, smem_bytes>>>(
        x, y, b0, b1, b2, a1, a2, total_chunks);
}